// round 11
// baseline (speedup 1.0000x reference)
#include <cuda_runtime.h>
#include <math.h>
#include <stdint.h>

// Problem constants (fixed by the dataset)
#define NN 16384      // nodes per set
#define DD 256        // model dim
#define EE 131072     // edges per relation
#define HH 8          // heads
#define HDIM 32       // head dim
#define IM 682        // SwiGLU intermediate
#define IM2 1364      // 2*IM (combined h1|h2 row stride)

// ---------------- scratch (static device globals; no allocations) ----------
__device__ float g_q[NN * DD];          // q (contiguous [n][h*32+d])
__device__ float g_k[NN * DD];          // k
__device__ float g_v[NN * DD];          // v
__device__ float g_kvtmp[NN * 3 * DD];  // raw interleaved kv / qkv GEMM output
__device__ float g_scores[EE * HH];     // edge scores; reused as concat-W in stage 3
__device__ float g_s[NN * HH];
__device__ float g_agg[NN * DD];
__device__ float g_x1[NN * DD];
__device__ float g_x2[NN * DD];
__device__ float g_tmp[NN * DD];
__device__ float g_hc[NN * IM2];        // combined [n][h1(682) | h2(682)]

__device__ __forceinline__ uint32_t f2tf32(float f) {
    uint32_t r;
    asm("cvt.rna.tf32.f32 %0, %1;" : "=r"(r) : "f"(f));
    return r;
}

// ---------------- TF32 tensor-core GEMM: reg prefetch + double buffering ----
// C[M,N] = A[M,K] @ B[K,N], row-major fp32 in/out, tf32 mma.sync compute.
// 128x128 block tile, BK=32, 256 threads (8 warps), warp tile 64x32.
// ACT=1: A is g_hc with row stride IM2; element = silu(hc[r][k]) * hc[r][682+k].
#define BM 128
#define BN 128
#define BK 32
#define PAD 132   // padded row length (floats), proven conflict pattern
#define SM_BUF (BK * PAD)                     // words per (As|Bs) buffer
#define SMEM_BYTES (4 * SM_BUF * 2 * 2)       // 2 arrays x 2 buffers = 67584 B

template <int ACT>
__global__ __launch_bounds__(256)
void tgemm_kernel(const float* __restrict__ A, const float* __restrict__ B,
                  float* __restrict__ C, int M, int N, int K) {
    extern __shared__ uint32_t smem[];
    uint32_t* AsBuf[2] = { smem,              smem + SM_BUF };
    uint32_t* BsBuf[2] = { smem + 2 * SM_BUF, smem + 3 * SM_BUF };

    const int tid  = threadIdx.x;
    const int lane = tid & 31;
    const int wid  = tid >> 5;            // 0..7
    const int warpM = wid & 1;            // 2 warps along M
    const int warpN = wid >> 1;           // 4 warps along N
    const int g   = lane >> 2;            // groupID 0..7
    const int tig = lane & 3;             // thread-in-group 0..3

    const int rowBase = blockIdx.y * BM;
    const int colBase = blockIdx.x * BN;

    float acc[4][4][4];
    #pragma unroll
    for (int i = 0; i < 4; i++)
        #pragma unroll
        for (int j = 0; j < 4; j++)
            #pragma unroll
            for (int r = 0; r < 4; r++) acc[i][j][r] = 0.0f;

    float2 aReg[8], bReg[8];
    const int T = (K + BK - 1) / BK;

    // A element loader: plain row-major, or fused SwiGLU activation from hc
    auto loadA = [&](int gr, int gk) -> float2 {
        if (gr >= M || gk >= K) return make_float2(0.0f, 0.0f);
        if (ACT == 0) {
            return *(const float2*)(A + (size_t)gr * K + gk);
        } else {
            float2 x = *(const float2*)(A + (size_t)gr * IM2 + gk);
            float2 y = *(const float2*)(A + (size_t)gr * IM2 + IM + gk);
            float2 r;
            r.x = x.x * (1.0f / (1.0f + __expf(-x.x))) * y.x;
            r.y = x.y * (1.0f / (1.0f + __expf(-x.y))) * y.y;
            return r;
        }
    };

    // ---- prologue: load tile 0 into registers, store to buffer 0
    #pragma unroll
    for (int i = 0; i < 8; i++) {
        int l  = tid + i * 256;
        int r  = l >> 4;
        int c2 = l & 15;
        aReg[i] = loadA(rowBase + r, 2 * c2);
    }
    #pragma unroll
    for (int i = 0; i < 8; i++) {
        int l  = tid + i * 256;
        int kk = l >> 6;
        int c2 = l & 63;
        int gk = kk, gc = colBase + 2 * c2;
        bReg[i] = (gk < K && gc < N) ? *(const float2*)(B + (size_t)gk * N + gc)
                                     : make_float2(0.0f, 0.0f);
    }
    {
        uint32_t* As0 = AsBuf[0];
        uint32_t* Bs0 = BsBuf[0];
        #pragma unroll
        for (int i = 0; i < 8; i++) {
            int l  = tid + i * 256;
            int r  = l >> 4;
            int c2 = l & 15;
            As0[(2 * c2) * PAD + r]     = f2tf32(aReg[i].x);
            As0[(2 * c2 + 1) * PAD + r] = f2tf32(aReg[i].y);
        }
        #pragma unroll
        for (int i = 0; i < 8; i++) {
            int l  = tid + i * 256;
            int kk = l >> 6;
            int c2 = l & 63;
            Bs0[kk * PAD + 2 * c2]     = f2tf32(bReg[i].x);
            Bs0[kk * PAD + 2 * c2 + 1] = f2tf32(bReg[i].y);
        }
    }
    __syncthreads();

    for (int t = 0; t < T; t++) {
        const int cur = t & 1, nxt = cur ^ 1;
        const uint32_t* As = AsBuf[cur];
        const uint32_t* Bs = BsBuf[cur];

        // ---- prefetch next tile into registers (overlaps compute below)
        if (t + 1 < T) {
            int k0 = (t + 1) * BK;
            #pragma unroll
            for (int i = 0; i < 8; i++) {
                int l  = tid + i * 256;
                int r  = l >> 4;
                int c2 = l & 15;
                aReg[i] = loadA(rowBase + r, k0 + 2 * c2);
            }
            #pragma unroll
            for (int i = 0; i < 8; i++) {
                int l  = tid + i * 256;
                int kk = l >> 6;
                int c2 = l & 63;
                int gk = k0 + kk, gc = colBase + 2 * c2;
                bReg[i] = (gk < K && gc < N) ? *(const float2*)(B + (size_t)gk * N + gc)
                                             : make_float2(0.0f, 0.0f);
            }
        }

        // ---- compute on current buffer: 4 k-atoms of 8
        #pragma unroll
        for (int ka = 0; ka < 4; ka++) {
            const int kb = ka * 8;
            uint32_t a[4][4], b[4][2];
            #pragma unroll
            for (int ma = 0; ma < 4; ma++) {
                int m0 = warpM * 64 + ma * 16;
                a[ma][0] = As[(kb + tig) * PAD + m0 + g];
                a[ma][1] = As[(kb + tig) * PAD + m0 + g + 8];
                a[ma][2] = As[(kb + tig + 4) * PAD + m0 + g];
                a[ma][3] = As[(kb + tig + 4) * PAD + m0 + g + 8];
            }
            #pragma unroll
            for (int na = 0; na < 4; na++) {
                int n0 = warpN * 32 + na * 8;
                b[na][0] = Bs[(kb + tig) * PAD + n0 + g];
                b[na][1] = Bs[(kb + tig + 4) * PAD + n0 + g];
            }
            #pragma unroll
            for (int ma = 0; ma < 4; ma++)
                #pragma unroll
                for (int na = 0; na < 4; na++) {
                    asm volatile(
                        "mma.sync.aligned.m16n8k8.row.col.f32.tf32.tf32.f32 "
                        "{%0,%1,%2,%3}, {%4,%5,%6,%7}, {%8,%9}, {%0,%1,%2,%3};\n"
                        : "+f"(acc[ma][na][0]), "+f"(acc[ma][na][1]),
                          "+f"(acc[ma][na][2]), "+f"(acc[ma][na][3])
                        : "r"(a[ma][0]), "r"(a[ma][1]), "r"(a[ma][2]), "r"(a[ma][3]),
                          "r"(b[na][0]), "r"(b[na][1]));
                }
        }

        // ---- store prefetched tile into the other buffer
        if (t + 1 < T) {
            uint32_t* An = AsBuf[nxt];
            uint32_t* Bn = BsBuf[nxt];
            #pragma unroll
            for (int i = 0; i < 8; i++) {
                int l  = tid + i * 256;
                int r  = l >> 4;
                int c2 = l & 15;
                An[(2 * c2) * PAD + r]     = f2tf32(aReg[i].x);
                An[(2 * c2 + 1) * PAD + r] = f2tf32(aReg[i].y);
            }
            #pragma unroll
            for (int i = 0; i < 8; i++) {
                int l  = tid + i * 256;
                int kk = l >> 6;
                int c2 = l & 63;
                Bn[kk * PAD + 2 * c2]     = f2tf32(bReg[i].x);
                Bn[kk * PAD + 2 * c2 + 1] = f2tf32(bReg[i].y);
            }
        }
        __syncthreads();
    }

    // ---- store C (float2 per row-half of each atom); N even -> alignment OK
    #pragma unroll
    for (int ma = 0; ma < 4; ma++) {
        int r0 = rowBase + warpM * 64 + ma * 16 + g;
        #pragma unroll
        for (int na = 0; na < 4; na++) {
            int c = colBase + warpN * 32 + na * 8 + tig * 2;
            if (c < N) {
                if (r0 < M)
                    *(float2*)(C + (size_t)r0 * N + c) = make_float2(acc[ma][na][0], acc[ma][na][1]);
                if (r0 + 8 < M)
                    *(float2*)(C + (size_t)(r0 + 8) * N + c) = make_float2(acc[ma][na][2], acc[ma][na][3]);
            }
        }
    }
}

// ---------------- concat ffn weights: Bc[k][c] = c<682 ? win[k][c] : v[k][c-682]
__global__ void concat_w_kernel(const float* __restrict__ win, const float* __restrict__ v,
                                float* __restrict__ Bc) {
    int i = blockIdx.x * blockDim.x + threadIdx.x;   // DD*IM2 threads
    if (i >= DD * IM2) return;
    int k = i / IM2, c = i % IM2;
    Bc[i] = (c < IM) ? win[k * IM + c] : v[k * IM + (c - IM)];
}

// ---------------- de-interleave kernels -------------------------------------
__global__ void deint_kv_kernel(const float* __restrict__ kv,
                                float* __restrict__ k, float* __restrict__ v) {
    int i = blockIdx.x * blockDim.x + threadIdx.x;   // NN*DD threads
    int n = i >> 8, j = i & 255;
    int h = j >> 5, d = j & 31;
    float2 p = *(const float2*)(kv + (size_t)n * 512 + h * 64 + 2 * d);
    k[i] = p.x;
    v[i] = p.y;
}

__global__ void deint_qkv_kernel(const float* __restrict__ qkv,
                                 float* __restrict__ q, float* __restrict__ k,
                                 float* __restrict__ v) {
    int i = blockIdx.x * blockDim.x + threadIdx.x;   // NN*DD threads
    int n = i >> 8, j = i & 255;
    int h = j >> 5, d = j & 31;
    const float* p = qkv + (size_t)n * 768 + h * 96 + 3 * d;
    q[i] = p[0];
    k[i] = p[1];
    v[i] = p[2];
}

// ---------------- reciprocal of softmax denominators ------------------------
__global__ void rcp_kernel(float* __restrict__ s) {
    int i = blockIdx.x * blockDim.x + threadIdx.x;
    if (i < NN * HH) s[i] = __frcp_rn(s[i]);
}

// ---------------- edge kernels (contiguous [n][h*32+d] layouts) -------------
__global__ void cross_scores_kernel(const float* __restrict__ Q, const float* __restrict__ Kk,
                                    const int* __restrict__ src, const int* __restrict__ dst,
                                    float* __restrict__ scores, float* __restrict__ s,
                                    float scale) {
    int e = (blockIdx.x * blockDim.x + threadIdx.x) >> 5;
    int lane = threadIdx.x & 31;
    if (e >= EE) return;
    int sn = src[e], tn = dst[e];
    const float4* q4 = (const float4*)(Q  + (size_t)tn * DD);
    const float4* k4 = (const float4*)(Kk + (size_t)sn * DD);
    float4 qa = q4[2 * lane], qb = q4[2 * lane + 1];
    float4 ka = k4[2 * lane], kb = k4[2 * lane + 1];
    float p = qa.x * ka.x + qa.y * ka.y + qa.z * ka.z + qa.w * ka.w
            + qb.x * kb.x + qb.y * kb.y + qb.z * kb.z + qb.w * kb.w;
    p += __shfl_xor_sync(0xFFFFFFFFu, p, 1);
    p += __shfl_xor_sync(0xFFFFFFFFu, p, 2);
    if ((lane & 3) == 0) {
        int h = lane >> 2;
        float ev = __expf(p * scale);
        scores[(size_t)e * HH + h] = ev;
        atomicAdd(&s[tn * HH + h], ev);
    }
}

__global__ void self_scores_kernel(const float* __restrict__ Q, const float* __restrict__ Kk,
                                   const float* __restrict__ attr,
                                   const int* __restrict__ src, const int* __restrict__ dst,
                                   float* __restrict__ scores, float* __restrict__ s) {
    int e = (blockIdx.x * blockDim.x + threadIdx.x) >> 5;
    int lane = threadIdx.x & 31;
    if (e >= EE) return;
    int sn = src[e], tn = dst[e];
    const float4* q4 = (const float4*)(Q    + (size_t)tn * DD);
    const float4* k4 = (const float4*)(Kk   + (size_t)sn * DD);
    const float4* a4 = (const float4*)(attr + (size_t)e  * DD);
    float4 qa = q4[2 * lane], qb = q4[2 * lane + 1];
    float4 ka = k4[2 * lane], kb = k4[2 * lane + 1];
    float4 aa = a4[2 * lane], ab = a4[2 * lane + 1];
    float p = qa.x * ka.x * aa.x + qa.y * ka.y * aa.y + qa.z * ka.z * aa.z + qa.w * ka.w * aa.w
            + qb.x * kb.x * ab.x + qb.y * kb.y * ab.y + qb.z * kb.z * ab.z + qb.w * kb.w * ab.w;
    p += __shfl_xor_sync(0xFFFFFFFFu, p, 1);
    p += __shfl_xor_sync(0xFFFFFFFFu, p, 2);
    if ((lane & 3) == 0) {
        int h = lane >> 2;
        float ev = __expf(p);   // no 1/sqrt(hd) in SelfMHA
        scores[(size_t)e * HH + h] = ev;
        atomicAdd(&s[tn * HH + h], ev);
    }
}

__global__ void agg_kernel(const float* __restrict__ scores, const float* __restrict__ rsum,
                           const float* __restrict__ V,
                           const int* __restrict__ src, const int* __restrict__ dst,
                           float* __restrict__ agg) {
    int e = (blockIdx.x * blockDim.x + threadIdx.x) >> 5;
    int lane = threadIdx.x & 31;
    if (e >= EE) return;
    int sn = src[e], tn = dst[e];
    const float* vp = V   + (size_t)sn * DD;
    float*       ap = agg + (size_t)tn * DD;
    const float* sp = scores + (size_t)e * HH;
    const float* rp = rsum + tn * HH;
    #pragma unroll
    for (int h = 0; h < HH; h++) {
        float w = sp[h] * rp[h];
        atomicAdd(ap + h * HDIM + lane, w * vp[h * HDIM + lane]);
    }
}

// ---------------- residual + RMSNorm: out = rmsnorm(a+b) * g ----------------
__global__ void add_rmsnorm_kernel(const float* __restrict__ a, const float* __restrict__ b,
                                   const float* __restrict__ g, float* __restrict__ out) {
    int row = blockIdx.x;
    int d = threadIdx.x;
    float x = a[(size_t)row * DD + d] + b[(size_t)row * DD + d];
    float v = x * x;
    __shared__ float red[8];
    #pragma unroll
    for (int o = 16; o; o >>= 1) v += __shfl_xor_sync(0xFFFFFFFFu, v, o);
    if ((d & 31) == 0) red[d >> 5] = v;
    __syncthreads();
    if (d < 8) {
        float t = red[d];
        #pragma unroll
        for (int o = 4; o; o >>= 1) t += __shfl_xor_sync(0xFFu, t, o);
        if (d == 0) red[0] = t;
    }
    __syncthreads();
    float norm = sqrtf(red[0]) * 0.0625f;
    float inv = 1.0f / fmaxf(norm, 1e-8f);
    out[(size_t)row * DD + d] = x * inv * g[d];
}

// ---------------- launch ----------------------------------------------------
static inline dim3 gg128(int M, int Ncols) { return dim3((Ncols + 127) / 128, (M + 127) / 128); }

extern "C" void kernel_launch(void* const* d_in, const int* in_sizes, int n_in,
                              void* d_out, int out_size) {
    const float* root      = (const float*)d_in[0];
    const float* node      = (const float*)d_in[1];
    const float* fringe    = (const float*)d_in[2];
    const int*   ntr_idx   = (const int*)d_in[3];
    const int*   rtr_idx   = (const int*)d_in[4];
    const int*   rtf_idx   = (const int*)d_in[5];
    const float* edge_attr = (const float*)d_in[6];
    const float* ntr_wq    = (const float*)d_in[7];
    const float* ntr_wkv   = (const float*)d_in[8];
    const float* ntr_wout  = (const float*)d_in[9];
    const float* ntr_g     = (const float*)d_in[10];
    const float* rtr_wqkv  = (const float*)d_in[11];
    const float* rtr_wout  = (const float*)d_in[12];
    const float* rtr_g     = (const float*)d_in[13];
    const float* ffn_win   = (const float*)d_in[14];
    const float* ffn_v     = (const float*)d_in[15];
    const float* ffn_wout  = (const float*)d_in[16];
    const float* ffn_g     = (const float*)d_in[17];
    const float* rtf_wq    = (const float*)d_in[18];
    const float* rtf_wkv   = (const float*)d_in[19];
    const float* rtf_wout  = (const float*)d_in[20];
    float* out = (float*)d_out;

    float *q, *k, *v, *kvtmp, *scores, *s, *agg, *x1, *x2, *tmp, *hc;
    cudaGetSymbolAddress((void**)&q,      g_q);
    cudaGetSymbolAddress((void**)&k,      g_k);
    cudaGetSymbolAddress((void**)&v,      g_v);
    cudaGetSymbolAddress((void**)&kvtmp,  g_kvtmp);
    cudaGetSymbolAddress((void**)&scores, g_scores);
    cudaGetSymbolAddress((void**)&s,      g_s);
    cudaGetSymbolAddress((void**)&agg,    g_agg);
    cudaGetSymbolAddress((void**)&x1,     g_x1);
    cudaGetSymbolAddress((void**)&x2,     g_x2);
    cudaGetSymbolAddress((void**)&tmp,    g_tmp);
    cudaGetSymbolAddress((void**)&hc,     g_hc);

    cudaFuncSetAttribute(tgemm_kernel<0>, cudaFuncAttributeMaxDynamicSharedMemorySize, SMEM_BYTES);
    cudaFuncSetAttribute(tgemm_kernel<1>, cudaFuncAttributeMaxDynamicSharedMemorySize, SMEM_BYTES);

    const float iscale = 0.17677669529663687f;  // 1/sqrt(32)
    const int edgeBlocks = EE / 8;
    const int ndBlocks = (NN * DD) / 256;
    const int nhBlocks = (NN * HH) / 256;

    // ===== stage 1: nodes_to_root CrossMHA + residual rmsnorm -> x1 =====
    tgemm_kernel<0><<<gg128(NN, DD), 256, SMEM_BYTES>>>(root, ntr_wq, q, NN, DD, DD);
    tgemm_kernel<0><<<gg128(NN, 2 * DD), 256, SMEM_BYTES>>>(node, ntr_wkv, kvtmp, NN, 2 * DD, DD);
    deint_kv_kernel<<<ndBlocks, 256>>>(kvtmp, k, v);
    cudaMemsetAsync(agg, 0, (size_t)NN * DD * sizeof(float));
    cudaMemsetAsync(s, 0, (size_t)NN * HH * sizeof(float));
    cross_scores_kernel<<<edgeBlocks, 256>>>(q, k, ntr_idx, ntr_idx + EE, scores, s, iscale);
    rcp_kernel<<<nhBlocks, 256>>>(s);
    agg_kernel<<<edgeBlocks, 256>>>(scores, s, v, ntr_idx, ntr_idx + EE, agg);
    tgemm_kernel<0><<<gg128(NN, DD), 256, SMEM_BYTES>>>(agg, ntr_wout, tmp, NN, DD, DD);
    add_rmsnorm_kernel<<<NN, 256>>>(root, tmp, ntr_g, x1);

    // ===== stage 2: roots_to_root SelfMHA + residual rmsnorm -> x2 =====
    tgemm_kernel<0><<<gg128(NN, 3 * DD), 256, SMEM_BYTES>>>(x1, rtr_wqkv, kvtmp, NN, 3 * DD, DD);
    deint_qkv_kernel<<<ndBlocks, 256>>>(kvtmp, q, k, v);
    cudaMemsetAsync(agg, 0, (size_t)NN * DD * sizeof(float));
    cudaMemsetAsync(s, 0, (size_t)NN * HH * sizeof(float));
    self_scores_kernel<<<edgeBlocks, 256>>>(q, k, edge_attr, rtr_idx, rtr_idx + EE, scores, s);
    rcp_kernel<<<nhBlocks, 256>>>(s);
    agg_kernel<<<edgeBlocks, 256>>>(scores, s, v, rtr_idx, rtr_idx + EE, agg);
    tgemm_kernel<0><<<gg128(NN, DD), 256, SMEM_BYTES>>>(agg, rtr_wout, tmp, NN, DD, DD);
    add_rmsnorm_kernel<<<NN, 256>>>(x1, tmp, rtr_g, x2);

    // ===== stage 3: SwiGLU FFN (on root_features) + residual rmsnorm -> out =====
    // scores buffer (4 MB) is free here; reuse as concatenated weights [DD][IM2]
    concat_w_kernel<<<(DD * IM2 + 255) / 256, 256>>>(ffn_win, ffn_v, scores);
    tgemm_kernel<0><<<gg128(NN, IM2), 256, SMEM_BYTES>>>(root, scores, hc, NN, IM2, DD);
    tgemm_kernel<1><<<gg128(NN, DD), 256, SMEM_BYTES>>>(hc, ffn_wout, tmp, NN, DD, IM);
    add_rmsnorm_kernel<<<NN, 256>>>(tmp, x2, ffn_g, out);

    // ===== stage 4: root_to_fringe CrossMHA -> out[N*D : 2*N*D] =====
    tgemm_kernel<0><<<gg128(NN, DD), 256, SMEM_BYTES>>>(fringe, rtf_wq, q, NN, DD, DD);
    tgemm_kernel<0><<<gg128(NN, 2 * DD), 256, SMEM_BYTES>>>(root, rtf_wkv, kvtmp, NN, 2 * DD, DD);
    deint_kv_kernel<<<ndBlocks, 256>>>(kvtmp, k, v);
    cudaMemsetAsync(agg, 0, (size_t)NN * DD * sizeof(float));
    cudaMemsetAsync(s, 0, (size_t)NN * HH * sizeof(float));
    cross_scores_kernel<<<edgeBlocks, 256>>>(q, k, rtf_idx, rtf_idx + EE, scores, s, iscale);
    rcp_kernel<<<nhBlocks, 256>>>(s);
    agg_kernel<<<edgeBlocks, 256>>>(scores, s, v, rtf_idx, rtf_idx + EE, agg);
    tgemm_kernel<0><<<gg128(NN, DD), 256, SMEM_BYTES>>>(agg, rtf_wout, out + (size_t)NN * DD, NN, DD, DD);
}

// round 14
// speedup vs baseline: 1.0605x; 1.0605x over previous
#include <cuda_runtime.h>
#include <math.h>
#include <stdint.h>

// Problem constants (fixed by the dataset)
#define NN 16384      // nodes per set
#define DD 256        // model dim
#define EE 131072     // edges per relation
#define HH 8          // heads
#define HDIM 32       // head dim
#define IM 682        // SwiGLU intermediate
#define IM2 1364      // 2*IM (combined h1|h2 row stride)

// ---------------- scratch (static device globals; no allocations) ----------
__device__ float g_q[NN * DD];          // q (contiguous [n][h*32+d])
__device__ float g_k[NN * DD];          // k
__device__ float g_v[NN * DD];          // v
__device__ float g_kvtmp[NN * 3 * DD];  // interleaved kv/qkv GEMM output
__device__ float g_scores[EE * HH];     // edge scores
__device__ float g_s[NN * HH];
__device__ float g_agg[NN * DD];
__device__ float g_x1[NN * DD];
__device__ float g_x2[NN * DD];
__device__ float g_tmp[NN * DD];
__device__ float g_hc[NN * IM2];        // combined [n][h1(682) | h2(682)]
__device__ float g_h1[NN * IM];         // activated h1 (dedicated, no aliasing)
__device__ float g_wc[DD * IM2];        // concatenated ffn weights (dedicated)

__device__ __forceinline__ uint32_t f2tf32(float f) {
    uint32_t r;
    asm("cvt.rna.tf32.f32 %0, %1;" : "=r"(r) : "f"(f));
    return r;
}

// ---------------- TF32 tensor-core GEMM: reg prefetch + double buffering ----
// C[M,N] = A[M,K] @ B[K,N], row-major fp32 in/out, tf32 mma.sync compute.
// 128x128 block tile, BK=32, 256 threads (8 warps), warp tile 64x32.
#define BM 128
#define BN 128
#define BK 32
#define PAD 132   // padded row length (floats), proven conflict pattern
#define SM_BUF (BK * PAD)                     // words per (As|Bs) buffer
#define SMEM_BYTES (4 * SM_BUF * 2 * 2)       // 2 arrays x 2 buffers = 67584 B

__global__ __launch_bounds__(256)
void tgemm_kernel(const float* __restrict__ A, const float* __restrict__ B,
                  float* __restrict__ C, int M, int N, int K) {
    extern __shared__ uint32_t smem[];
    uint32_t* AsBuf[2] = { smem,              smem + SM_BUF };
    uint32_t* BsBuf[2] = { smem + 2 * SM_BUF, smem + 3 * SM_BUF };

    const int tid  = threadIdx.x;
    const int lane = tid & 31;
    const int wid  = tid >> 5;            // 0..7
    const int warpM = wid & 1;            // 2 warps along M
    const int warpN = wid >> 1;           // 4 warps along N
    const int g   = lane >> 2;            // groupID 0..7
    const int tig = lane & 3;             // thread-in-group 0..3

    const int rowBase = blockIdx.y * BM;
    const int colBase = blockIdx.x * BN;

    float acc[4][4][4];
    #pragma unroll
    for (int i = 0; i < 4; i++)
        #pragma unroll
        for (int j = 0; j < 4; j++)
            #pragma unroll
            for (int r = 0; r < 4; r++) acc[i][j][r] = 0.0f;

    float2 aReg[8], bReg[8];
    const int T = (K + BK - 1) / BK;

    // ---- prologue: load tile 0 into registers, store to buffer 0
    #pragma unroll
    for (int i = 0; i < 8; i++) {
        int l  = tid + i * 256;
        int r  = l >> 4;
        int c2 = l & 15;
        int gr = rowBase + r, gk = 2 * c2;
        aReg[i] = (gr < M && gk < K) ? *(const float2*)(A + (size_t)gr * K + gk)
                                     : make_float2(0.0f, 0.0f);
    }
    #pragma unroll
    for (int i = 0; i < 8; i++) {
        int l  = tid + i * 256;
        int kk = l >> 6;
        int c2 = l & 63;
        int gk = kk, gc = colBase + 2 * c2;
        bReg[i] = (gk < K && gc < N) ? *(const float2*)(B + (size_t)gk * N + gc)
                                     : make_float2(0.0f, 0.0f);
    }
    {
        uint32_t* As0 = AsBuf[0];
        uint32_t* Bs0 = BsBuf[0];
        #pragma unroll
        for (int i = 0; i < 8; i++) {
            int l  = tid + i * 256;
            int r  = l >> 4;
            int c2 = l & 15;
            As0[(2 * c2) * PAD + r]     = f2tf32(aReg[i].x);
            As0[(2 * c2 + 1) * PAD + r] = f2tf32(aReg[i].y);
        }
        #pragma unroll
        for (int i = 0; i < 8; i++) {
            int l  = tid + i * 256;
            int kk = l >> 6;
            int c2 = l & 63;
            Bs0[kk * PAD + 2 * c2]     = f2tf32(bReg[i].x);
            Bs0[kk * PAD + 2 * c2 + 1] = f2tf32(bReg[i].y);
        }
    }
    __syncthreads();

    for (int t = 0; t < T; t++) {
        const int cur = t & 1, nxt = cur ^ 1;
        const uint32_t* As = AsBuf[cur];
        const uint32_t* Bs = BsBuf[cur];

        // ---- prefetch next tile into registers (overlaps compute below)
        if (t + 1 < T) {
            int k0 = (t + 1) * BK;
            #pragma unroll
            for (int i = 0; i < 8; i++) {
                int l  = tid + i * 256;
                int r  = l >> 4;
                int c2 = l & 15;
                int gr = rowBase + r, gk = k0 + 2 * c2;
                aReg[i] = (gr < M && gk < K) ? *(const float2*)(A + (size_t)gr * K + gk)
                                             : make_float2(0.0f, 0.0f);
            }
            #pragma unroll
            for (int i = 0; i < 8; i++) {
                int l  = tid + i * 256;
                int kk = l >> 6;
                int c2 = l & 63;
                int gk = k0 + kk, gc = colBase + 2 * c2;
                bReg[i] = (gk < K && gc < N) ? *(const float2*)(B + (size_t)gk * N + gc)
                                             : make_float2(0.0f, 0.0f);
            }
        }

        // ---- compute on current buffer: 4 k-atoms of 8
        #pragma unroll
        for (int ka = 0; ka < 4; ka++) {
            const int kb = ka * 8;
            uint32_t a[4][4], b[4][2];
            #pragma unroll
            for (int ma = 0; ma < 4; ma++) {
                int m0 = warpM * 64 + ma * 16;
                a[ma][0] = As[(kb + tig) * PAD + m0 + g];
                a[ma][1] = As[(kb + tig) * PAD + m0 + g + 8];
                a[ma][2] = As[(kb + tig + 4) * PAD + m0 + g];
                a[ma][3] = As[(kb + tig + 4) * PAD + m0 + g + 8];
            }
            #pragma unroll
            for (int na = 0; na < 4; na++) {
                int n0 = warpN * 32 + na * 8;
                b[na][0] = Bs[(kb + tig) * PAD + n0 + g];
                b[na][1] = Bs[(kb + tig + 4) * PAD + n0 + g];
            }
            #pragma unroll
            for (int ma = 0; ma < 4; ma++)
                #pragma unroll
                for (int na = 0; na < 4; na++) {
                    asm volatile(
                        "mma.sync.aligned.m16n8k8.row.col.f32.tf32.tf32.f32 "
                        "{%0,%1,%2,%3}, {%4,%5,%6,%7}, {%8,%9}, {%0,%1,%2,%3};\n"
                        : "+f"(acc[ma][na][0]), "+f"(acc[ma][na][1]),
                          "+f"(acc[ma][na][2]), "+f"(acc[ma][na][3])
                        : "r"(a[ma][0]), "r"(a[ma][1]), "r"(a[ma][2]), "r"(a[ma][3]),
                          "r"(b[na][0]), "r"(b[na][1]));
                }
        }

        // ---- store prefetched tile into the other buffer
        if (t + 1 < T) {
            uint32_t* An = AsBuf[nxt];
            uint32_t* Bn = BsBuf[nxt];
            #pragma unroll
            for (int i = 0; i < 8; i++) {
                int l  = tid + i * 256;
                int r  = l >> 4;
                int c2 = l & 15;
                An[(2 * c2) * PAD + r]     = f2tf32(aReg[i].x);
                An[(2 * c2 + 1) * PAD + r] = f2tf32(aReg[i].y);
            }
            #pragma unroll
            for (int i = 0; i < 8; i++) {
                int l  = tid + i * 256;
                int kk = l >> 6;
                int c2 = l & 63;
                Bn[kk * PAD + 2 * c2]     = f2tf32(bReg[i].x);
                Bn[kk * PAD + 2 * c2 + 1] = f2tf32(bReg[i].y);
            }
        }
        __syncthreads();
    }

    // ---- store C (float2 per row-half of each atom); N even -> alignment OK
    #pragma unroll
    for (int ma = 0; ma < 4; ma++) {
        int r0 = rowBase + warpM * 64 + ma * 16 + g;
        #pragma unroll
        for (int na = 0; na < 4; na++) {
            int c = colBase + warpN * 32 + na * 8 + tig * 2;
            if (c < N) {
                if (r0 < M)
                    *(float2*)(C + (size_t)r0 * N + c) = make_float2(acc[ma][na][0], acc[ma][na][1]);
                if (r0 + 8 < M)
                    *(float2*)(C + (size_t)(r0 + 8) * N + c) = make_float2(acc[ma][na][2], acc[ma][na][3]);
            }
        }
    }
}

// ---------------- concat ffn weights: Bc[k][c] = c<682 ? win[k][c] : v[k][c-682]
__global__ void concat_w_kernel(const float* __restrict__ win, const float* __restrict__ v,
                                float* __restrict__ Bc) {
    int i = blockIdx.x * blockDim.x + threadIdx.x;   // DD*IM2 threads
    if (i >= DD * IM2) return;
    int k = i / IM2, c = i % IM2;
    Bc[i] = (c < IM) ? win[k * IM + c] : v[k * IM + (c - IM)];
}

// ---------------- de-interleave kernels -------------------------------------
__global__ void deint_kv_kernel(const float* __restrict__ kv,
                                float* __restrict__ k, float* __restrict__ v) {
    int i = blockIdx.x * blockDim.x + threadIdx.x;   // NN*DD threads
    int n = i >> 8, j = i & 255;
    int h = j >> 5, d = j & 31;
    float2 p = *(const float2*)(kv + (size_t)n * 512 + h * 64 + 2 * d);
    k[i] = p.x;
    v[i] = p.y;
}

__global__ void deint_qkv_kernel(const float* __restrict__ qkv,
                                 float* __restrict__ q, float* __restrict__ k,
                                 float* __restrict__ v) {
    int i = blockIdx.x * blockDim.x + threadIdx.x;   // NN*DD threads
    int n = i >> 8, j = i & 255;
    int h = j >> 5, d = j & 31;
    const float* p = qkv + (size_t)n * 768 + h * 96 + 3 * d;
    q[i] = p[0];
    k[i] = p[1];
    v[i] = p[2];
}

// ---------------- reciprocal of softmax denominators ------------------------
__global__ void rcp_kernel(float* __restrict__ s) {
    int i = blockIdx.x * blockDim.x + threadIdx.x;
    if (i < NN * HH) s[i] = __frcp_rn(s[i]);
}

// ---------------- edge kernels (contiguous [n][h*32+d] layouts) -------------
__global__ void cross_scores_kernel(const float* __restrict__ Q, const float* __restrict__ Kk,
                                    const int* __restrict__ src, const int* __restrict__ dst,
                                    float* __restrict__ scores, float* __restrict__ s,
                                    float scale) {
    int e = (blockIdx.x * blockDim.x + threadIdx.x) >> 5;
    int lane = threadIdx.x & 31;
    if (e >= EE) return;
    int sn = src[e], tn = dst[e];
    const float4* q4 = (const float4*)(Q  + (size_t)tn * DD);
    const float4* k4 = (const float4*)(Kk + (size_t)sn * DD);
    float4 qa = q4[2 * lane], qb = q4[2 * lane + 1];
    float4 ka = k4[2 * lane], kb = k4[2 * lane + 1];
    float p = qa.x * ka.x + qa.y * ka.y + qa.z * ka.z + qa.w * ka.w
            + qb.x * kb.x + qb.y * kb.y + qb.z * kb.z + qb.w * kb.w;
    p += __shfl_xor_sync(0xFFFFFFFFu, p, 1);
    p += __shfl_xor_sync(0xFFFFFFFFu, p, 2);
    if ((lane & 3) == 0) {
        int h = lane >> 2;
        float ev = __expf(p * scale);
        scores[(size_t)e * HH + h] = ev;
        atomicAdd(&s[tn * HH + h], ev);
    }
}

__global__ void self_scores_kernel(const float* __restrict__ Q, const float* __restrict__ Kk,
                                   const float* __restrict__ attr,
                                   const int* __restrict__ src, const int* __restrict__ dst,
                                   float* __restrict__ scores, float* __restrict__ s) {
    int e = (blockIdx.x * blockDim.x + threadIdx.x) >> 5;
    int lane = threadIdx.x & 31;
    if (e >= EE) return;
    int sn = src[e], tn = dst[e];
    const float4* q4 = (const float4*)(Q    + (size_t)tn * DD);
    const float4* k4 = (const float4*)(Kk   + (size_t)sn * DD);
    const float4* a4 = (const float4*)(attr + (size_t)e  * DD);
    float4 qa = q4[2 * lane], qb = q4[2 * lane + 1];
    float4 ka = k4[2 * lane], kb = k4[2 * lane + 1];
    float4 aa = a4[2 * lane], ab = a4[2 * lane + 1];
    float p = qa.x * ka.x * aa.x + qa.y * ka.y * aa.y + qa.z * ka.z * aa.z + qa.w * ka.w * aa.w
            + qb.x * kb.x * ab.x + qb.y * kb.y * ab.y + qb.z * kb.z * ab.z + qb.w * kb.w * ab.w;
    p += __shfl_xor_sync(0xFFFFFFFFu, p, 1);
    p += __shfl_xor_sync(0xFFFFFFFFu, p, 2);
    if ((lane & 3) == 0) {
        int h = lane >> 2;
        float ev = __expf(p);   // no 1/sqrt(hd) in SelfMHA
        scores[(size_t)e * HH + h] = ev;
        atomicAdd(&s[tn * HH + h], ev);
    }
}

__global__ void agg_kernel(const float* __restrict__ scores, const float* __restrict__ rsum,
                           const float* __restrict__ V,
                           const int* __restrict__ src, const int* __restrict__ dst,
                           float* __restrict__ agg) {
    int e = (blockIdx.x * blockDim.x + threadIdx.x) >> 5;
    int lane = threadIdx.x & 31;
    if (e >= EE) return;
    int sn = src[e], tn = dst[e];
    const float* vp = V   + (size_t)sn * DD;
    float*       ap = agg + (size_t)tn * DD;
    const float* sp = scores + (size_t)e * HH;
    const float* rp = rsum + tn * HH;
    #pragma unroll
    for (int h = 0; h < HH; h++) {
        float w = sp[h] * rp[h];
        atomicAdd(ap + h * HDIM + lane, w * vp[h * HDIM + lane]);
    }
}

// ---------------- residual + RMSNorm: out = rmsnorm(a+b) * g ----------------
__global__ void add_rmsnorm_kernel(const float* __restrict__ a, const float* __restrict__ b,
                                   const float* __restrict__ g, float* __restrict__ out) {
    int row = blockIdx.x;
    int d = threadIdx.x;
    float x = a[(size_t)row * DD + d] + b[(size_t)row * DD + d];
    float v = x * x;
    __shared__ float red[8];
    #pragma unroll
    for (int o = 16; o; o >>= 1) v += __shfl_xor_sync(0xFFFFFFFFu, v, o);
    if ((d & 31) == 0) red[d >> 5] = v;
    __syncthreads();
    if (d < 8) {
        float t = red[d];
        #pragma unroll
        for (int o = 4; o; o >>= 1) t += __shfl_xor_sync(0xFFu, t, o);
        if (d == 0) red[0] = t;
    }
    __syncthreads();
    float norm = sqrtf(red[0]) * 0.0625f;
    float inv = 1.0f / fmaxf(norm, 1e-8f);
    out[(size_t)row * DD + d] = x * inv * g[d];
}

// ---------------- SwiGLU activation: h1[n][c] = silu(hc[n][c]) * hc[n][682+c]
__global__ void swiglu_act_kernel(const float* __restrict__ hc, float* __restrict__ h1) {
    int i = blockIdx.x * blockDim.x + threadIdx.x;   // NN*IM threads
    if (i >= NN * IM) return;
    int n = i / IM, c = i - n * IM;
    float x = hc[(size_t)n * IM2 + c];
    float y = hc[(size_t)n * IM2 + IM + c];
    h1[i] = x * (1.0f / (1.0f + __expf(-x))) * y;
}

// ---------------- launch ----------------------------------------------------
static inline dim3 gg128(int M, int Ncols) { return dim3((Ncols + 127) / 128, (M + 127) / 128); }

extern "C" void kernel_launch(void* const* d_in, const int* in_sizes, int n_in,
                              void* d_out, int out_size) {
    const float* root      = (const float*)d_in[0];
    const float* node      = (const float*)d_in[1];
    const float* fringe    = (const float*)d_in[2];
    const int*   ntr_idx   = (const int*)d_in[3];
    const int*   rtr_idx   = (const int*)d_in[4];
    const int*   rtf_idx   = (const int*)d_in[5];
    const float* edge_attr = (const float*)d_in[6];
    const float* ntr_wq    = (const float*)d_in[7];
    const float* ntr_wkv   = (const float*)d_in[8];
    const float* ntr_wout  = (const float*)d_in[9];
    const float* ntr_g     = (const float*)d_in[10];
    const float* rtr_wqkv  = (const float*)d_in[11];
    const float* rtr_wout  = (const float*)d_in[12];
    const float* rtr_g     = (const float*)d_in[13];
    const float* ffn_win   = (const float*)d_in[14];
    const float* ffn_v     = (const float*)d_in[15];
    const float* ffn_wout  = (const float*)d_in[16];
    const float* ffn_g     = (const float*)d_in[17];
    const float* rtf_wq    = (const float*)d_in[18];
    const float* rtf_wkv   = (const float*)d_in[19];
    const float* rtf_wout  = (const float*)d_in[20];
    float* out = (float*)d_out;

    float *q, *k, *v, *kvtmp, *scores, *s, *agg, *x1, *x2, *tmp, *hc, *h1, *wc;
    cudaGetSymbolAddress((void**)&q,      g_q);
    cudaGetSymbolAddress((void**)&k,      g_k);
    cudaGetSymbolAddress((void**)&v,      g_v);
    cudaGetSymbolAddress((void**)&kvtmp,  g_kvtmp);
    cudaGetSymbolAddress((void**)&scores, g_scores);
    cudaGetSymbolAddress((void**)&s,      g_s);
    cudaGetSymbolAddress((void**)&agg,    g_agg);
    cudaGetSymbolAddress((void**)&x1,     g_x1);
    cudaGetSymbolAddress((void**)&x2,     g_x2);
    cudaGetSymbolAddress((void**)&tmp,    g_tmp);
    cudaGetSymbolAddress((void**)&hc,     g_hc);
    cudaGetSymbolAddress((void**)&h1,     g_h1);
    cudaGetSymbolAddress((void**)&wc,     g_wc);

    cudaFuncSetAttribute(tgemm_kernel, cudaFuncAttributeMaxDynamicSharedMemorySize, SMEM_BYTES);

    const float iscale = 0.17677669529663687f;  // 1/sqrt(32)
    const int edgeBlocks = EE / 8;
    const int ndBlocks = (NN * DD) / 256;
    const int nhBlocks = (NN * HH) / 256;

    // ===== stage 1: nodes_to_root CrossMHA + residual rmsnorm -> x1 =====
    tgemm_kernel<<<gg128(NN, DD), 256, SMEM_BYTES>>>(root, ntr_wq, q, NN, DD, DD);
    tgemm_kernel<<<gg128(NN, 2 * DD), 256, SMEM_BYTES>>>(node, ntr_wkv, kvtmp, NN, 2 * DD, DD);
    deint_kv_kernel<<<ndBlocks, 256>>>(kvtmp, k, v);
    cudaMemsetAsync(agg, 0, (size_t)NN * DD * sizeof(float));
    cudaMemsetAsync(s, 0, (size_t)NN * HH * sizeof(float));
    cross_scores_kernel<<<edgeBlocks, 256>>>(q, k, ntr_idx, ntr_idx + EE, scores, s, iscale);
    rcp_kernel<<<nhBlocks, 256>>>(s);
    agg_kernel<<<edgeBlocks, 256>>>(scores, s, v, ntr_idx, ntr_idx + EE, agg);
    tgemm_kernel<<<gg128(NN, DD), 256, SMEM_BYTES>>>(agg, ntr_wout, tmp, NN, DD, DD);
    add_rmsnorm_kernel<<<NN, 256>>>(root, tmp, ntr_g, x1);

    // ===== stage 2: roots_to_root SelfMHA + residual rmsnorm -> x2 =====
    tgemm_kernel<<<gg128(NN, 3 * DD), 256, SMEM_BYTES>>>(x1, rtr_wqkv, kvtmp, NN, 3 * DD, DD);
    deint_qkv_kernel<<<ndBlocks, 256>>>(kvtmp, q, k, v);
    cudaMemsetAsync(agg, 0, (size_t)NN * DD * sizeof(float));
    cudaMemsetAsync(s, 0, (size_t)NN * HH * sizeof(float));
    self_scores_kernel<<<edgeBlocks, 256>>>(q, k, edge_attr, rtr_idx, rtr_idx + EE, scores, s);
    rcp_kernel<<<nhBlocks, 256>>>(s);
    agg_kernel<<<edgeBlocks, 256>>>(scores, s, v, rtr_idx, rtr_idx + EE, agg);
    tgemm_kernel<<<gg128(NN, DD), 256, SMEM_BYTES>>>(agg, rtr_wout, tmp, NN, DD, DD);
    add_rmsnorm_kernel<<<NN, 256>>>(x1, tmp, rtr_g, x2);

    // ===== stage 3: SwiGLU FFN (on root_features) + residual rmsnorm -> out =====
    concat_w_kernel<<<(DD * IM2 + 255) / 256, 256>>>(ffn_win, ffn_v, wc);
    tgemm_kernel<<<gg128(NN, IM2), 256, SMEM_BYTES>>>(root, wc, hc, NN, IM2, DD);
    swiglu_act_kernel<<<(NN * IM + 255) / 256, 256>>>(hc, h1);
    tgemm_kernel<<<gg128(NN, DD), 256, SMEM_BYTES>>>(h1, ffn_wout, tmp, NN, DD, IM);
    add_rmsnorm_kernel<<<NN, 256>>>(tmp, x2, ffn_g, out);

    // ===== stage 4: root_to_fringe CrossMHA -> out[N*D : 2*N*D] =====
    tgemm_kernel<<<gg128(NN, DD), 256, SMEM_BYTES>>>(fringe, rtf_wq, q, NN, DD, DD);
    tgemm_kernel<<<gg128(NN, 2 * DD), 256, SMEM_BYTES>>>(root, rtf_wkv, kvtmp, NN, 2 * DD, DD);
    deint_kv_kernel<<<ndBlocks, 256>>>(kvtmp, k, v);
    cudaMemsetAsync(agg, 0, (size_t)NN * DD * sizeof(float));
    cudaMemsetAsync(s, 0, (size_t)NN * HH * sizeof(float));
    cross_scores_kernel<<<edgeBlocks, 256>>>(q, k, rtf_idx, rtf_idx + EE, scores, s, iscale);
    rcp_kernel<<<nhBlocks, 256>>>(s);
    agg_kernel<<<edgeBlocks, 256>>>(scores, s, v, rtf_idx, rtf_idx + EE, agg);
    tgemm_kernel<<<gg128(NN, DD), 256, SMEM_BYTES>>>(agg, rtf_wout, out + (size_t)NN * DD, NN, DD, DD);
}

// round 16
// speedup vs baseline: 1.0816x; 1.0199x over previous
#include <cuda_runtime.h>
#include <math.h>
#include <stdint.h>

// Problem constants (fixed by the dataset)
#define NN 16384      // nodes per set
#define DD 256        // model dim
#define EE 131072     // edges per relation
#define HH 8          // heads
#define HDIM 32       // head dim
#define IM 682        // SwiGLU intermediate
#define IM2 1364      // 2*IM (combined h1|h2 row stride)

// ---------------- scratch (static device globals; no allocations) ----------
__device__ float g_q[NN * DD];          // q (contiguous [n][h*32+d])
__device__ float g_k[NN * DD];          // k
__device__ float g_v[NN * DD];          // v
__device__ float g_kvtmp[NN * 3 * DD];  // interleaved kv/qkv GEMM output
__device__ float g_s[NN * HH];
__device__ float g_agg[NN * DD];
__device__ float g_x1[NN * DD];
__device__ float g_x2[NN * DD];
__device__ float g_tmp[NN * DD];
__device__ float g_hc[NN * IM2];        // combined [n][h1(682) | h2(682)]
__device__ float g_h1[NN * IM];         // activated h1
__device__ float g_wc[DD * IM2];        // concatenated ffn weights

__device__ __forceinline__ uint32_t f2tf32(float f) {
    uint32_t r;
    asm("cvt.rna.tf32.f32 %0, %1;" : "=r"(r) : "f"(f));
    return r;
}

// ---------------- TF32 tensor-core GEMM: reg prefetch + double buffering ----
// C[M,N] = A[M,K] @ B[K,N], row-major fp32 in/out, tf32 mma.sync compute.
// 128x128 block tile, BK=32, 256 threads (8 warps), warp tile 64x32.
#define BM 128
#define BN 128
#define BK 32
#define PAD 132   // padded row length (floats), proven conflict pattern
#define SM_BUF (BK * PAD)                     // words per (As|Bs) buffer
#define SMEM_BYTES (4 * SM_BUF * 2 * 2)       // 2 arrays x 2 buffers = 67584 B

__global__ __launch_bounds__(256)
void tgemm_kernel(const float* __restrict__ A, const float* __restrict__ B,
                  float* __restrict__ C, int M, int N, int K) {
    extern __shared__ uint32_t smem[];
    uint32_t* AsBuf[2] = { smem,              smem + SM_BUF };
    uint32_t* BsBuf[2] = { smem + 2 * SM_BUF, smem + 3 * SM_BUF };

    const int tid  = threadIdx.x;
    const int lane = tid & 31;
    const int wid  = tid >> 5;            // 0..7
    const int warpM = wid & 1;            // 2 warps along M
    const int warpN = wid >> 1;           // 4 warps along N
    const int g   = lane >> 2;            // groupID 0..7
    const int tig = lane & 3;             // thread-in-group 0..3

    const int rowBase = blockIdx.y * BM;
    const int colBase = blockIdx.x * BN;

    float acc[4][4][4];
    #pragma unroll
    for (int i = 0; i < 4; i++)
        #pragma unroll
        for (int j = 0; j < 4; j++)
            #pragma unroll
            for (int r = 0; r < 4; r++) acc[i][j][r] = 0.0f;

    float2 aReg[8], bReg[8];
    const int T = (K + BK - 1) / BK;

    // ---- prologue: load tile 0 into registers, store to buffer 0
    #pragma unroll
    for (int i = 0; i < 8; i++) {
        int l  = tid + i * 256;
        int r  = l >> 4;
        int c2 = l & 15;
        int gr = rowBase + r, gk = 2 * c2;
        aReg[i] = (gr < M && gk < K) ? *(const float2*)(A + (size_t)gr * K + gk)
                                     : make_float2(0.0f, 0.0f);
    }
    #pragma unroll
    for (int i = 0; i < 8; i++) {
        int l  = tid + i * 256;
        int kk = l >> 6;
        int c2 = l & 63;
        int gk = kk, gc = colBase + 2 * c2;
        bReg[i] = (gk < K && gc < N) ? *(const float2*)(B + (size_t)gk * N + gc)
                                     : make_float2(0.0f, 0.0f);
    }
    {
        uint32_t* As0 = AsBuf[0];
        uint32_t* Bs0 = BsBuf[0];
        #pragma unroll
        for (int i = 0; i < 8; i++) {
            int l  = tid + i * 256;
            int r  = l >> 4;
            int c2 = l & 15;
            As0[(2 * c2) * PAD + r]     = f2tf32(aReg[i].x);
            As0[(2 * c2 + 1) * PAD + r] = f2tf32(aReg[i].y);
        }
        #pragma unroll
        for (int i = 0; i < 8; i++) {
            int l  = tid + i * 256;
            int kk = l >> 6;
            int c2 = l & 63;
            Bs0[kk * PAD + 2 * c2]     = f2tf32(bReg[i].x);
            Bs0[kk * PAD + 2 * c2 + 1] = f2tf32(bReg[i].y);
        }
    }
    __syncthreads();

    for (int t = 0; t < T; t++) {
        const int cur = t & 1, nxt = cur ^ 1;
        const uint32_t* As = AsBuf[cur];
        const uint32_t* Bs = BsBuf[cur];

        // ---- prefetch next tile into registers (overlaps compute below)
        if (t + 1 < T) {
            int k0 = (t + 1) * BK;
            #pragma unroll
            for (int i = 0; i < 8; i++) {
                int l  = tid + i * 256;
                int r  = l >> 4;
                int c2 = l & 15;
                int gr = rowBase + r, gk = k0 + 2 * c2;
                aReg[i] = (gr < M && gk < K) ? *(const float2*)(A + (size_t)gr * K + gk)
                                             : make_float2(0.0f, 0.0f);
            }
            #pragma unroll
            for (int i = 0; i < 8; i++) {
                int l  = tid + i * 256;
                int kk = l >> 6;
                int c2 = l & 63;
                int gk = k0 + kk, gc = colBase + 2 * c2;
                bReg[i] = (gk < K && gc < N) ? *(const float2*)(B + (size_t)gk * N + gc)
                                             : make_float2(0.0f, 0.0f);
            }
        }

        // ---- compute on current buffer: 4 k-atoms of 8
        #pragma unroll
        for (int ka = 0; ka < 4; ka++) {
            const int kb = ka * 8;
            uint32_t a[4][4], b[4][2];
            #pragma unroll
            for (int ma = 0; ma < 4; ma++) {
                int m0 = warpM * 64 + ma * 16;
                a[ma][0] = As[(kb + tig) * PAD + m0 + g];
                a[ma][1] = As[(kb + tig) * PAD + m0 + g + 8];
                a[ma][2] = As[(kb + tig + 4) * PAD + m0 + g];
                a[ma][3] = As[(kb + tig + 4) * PAD + m0 + g + 8];
            }
            #pragma unroll
            for (int na = 0; na < 4; na++) {
                int n0 = warpN * 32 + na * 8;
                b[na][0] = Bs[(kb + tig) * PAD + n0 + g];
                b[na][1] = Bs[(kb + tig + 4) * PAD + n0 + g];
            }
            #pragma unroll
            for (int ma = 0; ma < 4; ma++)
                #pragma unroll
                for (int na = 0; na < 4; na++) {
                    asm volatile(
                        "mma.sync.aligned.m16n8k8.row.col.f32.tf32.tf32.f32 "
                        "{%0,%1,%2,%3}, {%4,%5,%6,%7}, {%8,%9}, {%0,%1,%2,%3};\n"
                        : "+f"(acc[ma][na][0]), "+f"(acc[ma][na][1]),
                          "+f"(acc[ma][na][2]), "+f"(acc[ma][na][3])
                        : "r"(a[ma][0]), "r"(a[ma][1]), "r"(a[ma][2]), "r"(a[ma][3]),
                          "r"(b[na][0]), "r"(b[na][1]));
                }
        }

        // ---- store prefetched tile into the other buffer
        if (t + 1 < T) {
            uint32_t* An = AsBuf[nxt];
            uint32_t* Bn = BsBuf[nxt];
            #pragma unroll
            for (int i = 0; i < 8; i++) {
                int l  = tid + i * 256;
                int r  = l >> 4;
                int c2 = l & 15;
                An[(2 * c2) * PAD + r]     = f2tf32(aReg[i].x);
                An[(2 * c2 + 1) * PAD + r] = f2tf32(aReg[i].y);
            }
            #pragma unroll
            for (int i = 0; i < 8; i++) {
                int l  = tid + i * 256;
                int kk = l >> 6;
                int c2 = l & 63;
                Bn[kk * PAD + 2 * c2]     = f2tf32(bReg[i].x);
                Bn[kk * PAD + 2 * c2 + 1] = f2tf32(bReg[i].y);
            }
        }
        __syncthreads();
    }

    // ---- store C (float2 per row-half of each atom); N even -> alignment OK
    #pragma unroll
    for (int ma = 0; ma < 4; ma++) {
        int r0 = rowBase + warpM * 64 + ma * 16 + g;
        #pragma unroll
        for (int na = 0; na < 4; na++) {
            int c = colBase + warpN * 32 + na * 8 + tig * 2;
            if (c < N) {
                if (r0 < M)
                    *(float2*)(C + (size_t)r0 * N + c) = make_float2(acc[ma][na][0], acc[ma][na][1]);
                if (r0 + 8 < M)
                    *(float2*)(C + (size_t)(r0 + 8) * N + c) = make_float2(acc[ma][na][2], acc[ma][na][3]);
            }
        }
    }
}

// ---------------- concat ffn weights ----------------------------------------
__global__ void concat_w_kernel(const float* __restrict__ win, const float* __restrict__ v,
                                float* __restrict__ Bc) {
    int i = blockIdx.x * blockDim.x + threadIdx.x;   // DD*IM2 threads
    if (i >= DD * IM2) return;
    int k = i / IM2, c = i % IM2;
    Bc[i] = (c < IM) ? win[k * IM + c] : v[k * IM + (c - IM)];
}

// ---------------- de-interleave kernels -------------------------------------
__global__ void deint_kv_kernel(const float* __restrict__ kv,
                                float* __restrict__ k, float* __restrict__ v) {
    int i = blockIdx.x * blockDim.x + threadIdx.x;   // NN*DD threads
    int n = i >> 8, j = i & 255;
    int h = j >> 5, d = j & 31;
    float2 p = *(const float2*)(kv + (size_t)n * 512 + h * 64 + 2 * d);
    k[i] = p.x;
    v[i] = p.y;
}

__global__ void deint_qkv_kernel(const float* __restrict__ qkv,
                                 float* __restrict__ q, float* __restrict__ k,
                                 float* __restrict__ v) {
    int i = blockIdx.x * blockDim.x + threadIdx.x;   // NN*DD threads
    int n = i >> 8, j = i & 255;
    int h = j >> 5, d = j & 31;
    const float* p = qkv + (size_t)n * 768 + h * 96 + 3 * d;
    q[i] = p[0];
    k[i] = p[1];
    v[i] = p[2];
}

// ---------------- safe reciprocal of softmax denominators -------------------
// Nodes with NO incoming edges have s==0; reference yields 0 rows for them
// (empty segment_sum). Return 0 instead of inf so norm_agg gives 0, not NaN.
__global__ void rcp_kernel(float* __restrict__ s) {
    int i = blockIdx.x * blockDim.x + threadIdx.x;
    if (i < NN * HH) {
        float x = s[i];
        s[i] = (x > 0.0f) ? __frcp_rn(x) : 0.0f;
    }
}

// ---------------- normalize aggregated values by softmax denominator --------
__global__ void norm_agg_kernel(float* __restrict__ agg, const float* __restrict__ rs) {
    int i = blockIdx.x * blockDim.x + threadIdx.x;   // NN*DD threads
    int n = i >> 8, j = i & 255;
    agg[i] *= rs[n * HH + (j >> 5)];
}

// ---------------- FUSED edge kernels ----------------------------------------
// One pass per relation: compute score, exp, accumulate denominator AND the
// UNNORMALIZED weighted-V aggregate (softmax division deferred to norm_agg).
// Warp per edge. Score phase: 4 lanes per head, lane covers 8 dims (float4 x2).
// Agg phase: per head h, weight broadcast via shfl from lane 4h; 32 contiguous
// lanes per atomic instruction (1-2 cache lines).
__global__ void cross_fused_kernel(const float* __restrict__ Q, const float* __restrict__ Kk,
                                   const float* __restrict__ V,
                                   const int* __restrict__ src, const int* __restrict__ dst,
                                   float* __restrict__ s, float* __restrict__ agg,
                                   float scale) {
    int e = (blockIdx.x * blockDim.x + threadIdx.x) >> 5;
    int lane = threadIdx.x & 31;
    if (e >= EE) return;
    int sn = src[e], tn = dst[e];
    const float4* q4 = (const float4*)(Q  + (size_t)tn * DD);
    const float4* k4 = (const float4*)(Kk + (size_t)sn * DD);
    float4 qa = q4[2 * lane], qb = q4[2 * lane + 1];
    float4 ka = k4[2 * lane], kb = k4[2 * lane + 1];
    float p = qa.x * ka.x + qa.y * ka.y + qa.z * ka.z + qa.w * ka.w
            + qb.x * kb.x + qb.y * kb.y + qb.z * kb.z + qb.w * kb.w;
    p += __shfl_xor_sync(0xFFFFFFFFu, p, 1);
    p += __shfl_xor_sync(0xFFFFFFFFu, p, 2);
    float ev = __expf(p * scale);             // per-lane: own head's value
    if ((lane & 3) == 0)
        atomicAdd(&s[tn * HH + (lane >> 2)], ev);
    const float* vp = V   + (size_t)sn * DD;
    float*       ap = agg + (size_t)tn * DD;
    #pragma unroll
    for (int h = 0; h < HH; h++) {
        float w = __shfl_sync(0xFFFFFFFFu, ev, h * 4);
        atomicAdd(ap + h * HDIM + lane, w * vp[h * HDIM + lane]);
    }
}

__global__ void self_fused_kernel(const float* __restrict__ Q, const float* __restrict__ Kk,
                                  const float* __restrict__ V, const float* __restrict__ attr,
                                  const int* __restrict__ src, const int* __restrict__ dst,
                                  float* __restrict__ s, float* __restrict__ agg) {
    int e = (blockIdx.x * blockDim.x + threadIdx.x) >> 5;
    int lane = threadIdx.x & 31;
    if (e >= EE) return;
    int sn = src[e], tn = dst[e];
    const float4* q4 = (const float4*)(Q    + (size_t)tn * DD);
    const float4* k4 = (const float4*)(Kk   + (size_t)sn * DD);
    const float4* a4 = (const float4*)(attr + (size_t)e  * DD);
    float4 qa = q4[2 * lane], qb = q4[2 * lane + 1];
    float4 ka = k4[2 * lane], kb = k4[2 * lane + 1];
    float4 aa = a4[2 * lane], ab = a4[2 * lane + 1];
    float p = qa.x * ka.x * aa.x + qa.y * ka.y * aa.y + qa.z * ka.z * aa.z + qa.w * ka.w * aa.w
            + qb.x * kb.x * ab.x + qb.y * kb.y * ab.y + qb.z * kb.z * ab.z + qb.w * kb.w * ab.w;
    p += __shfl_xor_sync(0xFFFFFFFFu, p, 1);
    p += __shfl_xor_sync(0xFFFFFFFFu, p, 2);
    float ev = __expf(p);                     // no 1/sqrt(hd) in SelfMHA
    if ((lane & 3) == 0)
        atomicAdd(&s[tn * HH + (lane >> 2)], ev);
    const float* vp = V   + (size_t)sn * DD;
    float*       ap = agg + (size_t)tn * DD;
    #pragma unroll
    for (int h = 0; h < HH; h++) {
        float w = __shfl_sync(0xFFFFFFFFu, ev, h * 4);
        atomicAdd(ap + h * HDIM + lane, w * vp[h * HDIM + lane]);
    }
}

// ---------------- residual + RMSNorm: out = rmsnorm(a+b) * g ----------------
__global__ void add_rmsnorm_kernel(const float* __restrict__ a, const float* __restrict__ b,
                                   const float* __restrict__ g, float* __restrict__ out) {
    int row = blockIdx.x;
    int d = threadIdx.x;
    float x = a[(size_t)row * DD + d] + b[(size_t)row * DD + d];
    float v = x * x;
    __shared__ float red[8];
    #pragma unroll
    for (int o = 16; o; o >>= 1) v += __shfl_xor_sync(0xFFFFFFFFu, v, o);
    if ((d & 31) == 0) red[d >> 5] = v;
    __syncthreads();
    if (d < 8) {
        float t = red[d];
        #pragma unroll
        for (int o = 4; o; o >>= 1) t += __shfl_xor_sync(0xFFu, t, o);
        if (d == 0) red[0] = t;
    }
    __syncthreads();
    float norm = sqrtf(red[0]) * 0.0625f;
    float inv = 1.0f / fmaxf(norm, 1e-8f);
    out[(size_t)row * DD + d] = x * inv * g[d];
}

// ---------------- SwiGLU activation: h1[n][c] = silu(hc[n][c]) * hc[n][682+c]
__global__ void swiglu_act_kernel(const float* __restrict__ hc, float* __restrict__ h1) {
    int i = blockIdx.x * blockDim.x + threadIdx.x;   // NN*IM threads
    if (i >= NN * IM) return;
    int n = i / IM, c = i - n * IM;
    float x = hc[(size_t)n * IM2 + c];
    float y = hc[(size_t)n * IM2 + IM + c];
    h1[i] = x * (1.0f / (1.0f + __expf(-x))) * y;
}

// ---------------- launch ----------------------------------------------------
static inline dim3 gg128(int M, int Ncols) { return dim3((Ncols + 127) / 128, (M + 127) / 128); }

extern "C" void kernel_launch(void* const* d_in, const int* in_sizes, int n_in,
                              void* d_out, int out_size) {
    const float* root      = (const float*)d_in[0];
    const float* node      = (const float*)d_in[1];
    const float* fringe    = (const float*)d_in[2];
    const int*   ntr_idx   = (const int*)d_in[3];
    const int*   rtr_idx   = (const int*)d_in[4];
    const int*   rtf_idx   = (const int*)d_in[5];
    const float* edge_attr = (const float*)d_in[6];
    const float* ntr_wq    = (const float*)d_in[7];
    const float* ntr_wkv   = (const float*)d_in[8];
    const float* ntr_wout  = (const float*)d_in[9];
    const float* ntr_g     = (const float*)d_in[10];
    const float* rtr_wqkv  = (const float*)d_in[11];
    const float* rtr_wout  = (const float*)d_in[12];
    const float* rtr_g     = (const float*)d_in[13];
    const float* ffn_win   = (const float*)d_in[14];
    const float* ffn_v     = (const float*)d_in[15];
    const float* ffn_wout  = (const float*)d_in[16];
    const float* ffn_g     = (const float*)d_in[17];
    const float* rtf_wq    = (const float*)d_in[18];
    const float* rtf_wkv   = (const float*)d_in[19];
    const float* rtf_wout  = (const float*)d_in[20];
    float* out = (float*)d_out;

    float *q, *k, *v, *kvtmp, *s, *agg, *x1, *x2, *tmp, *hc, *h1, *wc;
    cudaGetSymbolAddress((void**)&q,      g_q);
    cudaGetSymbolAddress((void**)&k,      g_k);
    cudaGetSymbolAddress((void**)&v,      g_v);
    cudaGetSymbolAddress((void**)&kvtmp,  g_kvtmp);
    cudaGetSymbolAddress((void**)&s,      g_s);
    cudaGetSymbolAddress((void**)&agg,    g_agg);
    cudaGetSymbolAddress((void**)&x1,     g_x1);
    cudaGetSymbolAddress((void**)&x2,     g_x2);
    cudaGetSymbolAddress((void**)&tmp,    g_tmp);
    cudaGetSymbolAddress((void**)&hc,     g_hc);
    cudaGetSymbolAddress((void**)&h1,     g_h1);
    cudaGetSymbolAddress((void**)&wc,     g_wc);

    cudaFuncSetAttribute(tgemm_kernel, cudaFuncAttributeMaxDynamicSharedMemorySize, SMEM_BYTES);

    const float iscale = 0.17677669529663687f;  // 1/sqrt(32)
    const int edgeBlocks = EE / 8;
    const int ndBlocks = (NN * DD) / 256;
    const int nhBlocks = (NN * HH) / 256;

    // ===== stage 1: nodes_to_root CrossMHA + residual rmsnorm -> x1 =====
    tgemm_kernel<<<gg128(NN, DD), 256, SMEM_BYTES>>>(root, ntr_wq, q, NN, DD, DD);
    tgemm_kernel<<<gg128(NN, 2 * DD), 256, SMEM_BYTES>>>(node, ntr_wkv, kvtmp, NN, 2 * DD, DD);
    deint_kv_kernel<<<ndBlocks, 256>>>(kvtmp, k, v);
    cudaMemsetAsync(agg, 0, (size_t)NN * DD * sizeof(float));
    cudaMemsetAsync(s, 0, (size_t)NN * HH * sizeof(float));
    cross_fused_kernel<<<edgeBlocks, 256>>>(q, k, v, ntr_idx, ntr_idx + EE, s, agg, iscale);
    rcp_kernel<<<nhBlocks, 256>>>(s);
    norm_agg_kernel<<<ndBlocks, 256>>>(agg, s);
    tgemm_kernel<<<gg128(NN, DD), 256, SMEM_BYTES>>>(agg, ntr_wout, tmp, NN, DD, DD);
    add_rmsnorm_kernel<<<NN, 256>>>(root, tmp, ntr_g, x1);

    // ===== stage 2: roots_to_root SelfMHA + residual rmsnorm -> x2 =====
    tgemm_kernel<<<gg128(NN, 3 * DD), 256, SMEM_BYTES>>>(x1, rtr_wqkv, kvtmp, NN, 3 * DD, DD);
    deint_qkv_kernel<<<ndBlocks, 256>>>(kvtmp, q, k, v);
    cudaMemsetAsync(agg, 0, (size_t)NN * DD * sizeof(float));
    cudaMemsetAsync(s, 0, (size_t)NN * HH * sizeof(float));
    self_fused_kernel<<<edgeBlocks, 256>>>(q, k, v, edge_attr, rtr_idx, rtr_idx + EE, s, agg);
    rcp_kernel<<<nhBlocks, 256>>>(s);
    norm_agg_kernel<<<ndBlocks, 256>>>(agg, s);
    tgemm_kernel<<<gg128(NN, DD), 256, SMEM_BYTES>>>(agg, rtr_wout, tmp, NN, DD, DD);
    add_rmsnorm_kernel<<<NN, 256>>>(x1, tmp, rtr_g, x2);

    // ===== stage 3: SwiGLU FFN (on root_features) + residual rmsnorm -> out =====
    concat_w_kernel<<<(DD * IM2 + 255) / 256, 256>>>(ffn_win, ffn_v, wc);
    tgemm_kernel<<<gg128(NN, IM2), 256, SMEM_BYTES>>>(root, wc, hc, NN, IM2, DD);
    swiglu_act_kernel<<<(NN * IM + 255) / 256, 256>>>(hc, h1);
    tgemm_kernel<<<gg128(NN, DD), 256, SMEM_BYTES>>>(h1, ffn_wout, tmp, NN, DD, IM);
    add_rmsnorm_kernel<<<NN, 256>>>(tmp, x2, ffn_g, out);

    // ===== stage 4: root_to_fringe CrossMHA -> out[N*D : 2*N*D] =====
    tgemm_kernel<<<gg128(NN, DD), 256, SMEM_BYTES>>>(fringe, rtf_wq, q, NN, DD, DD);
    tgemm_kernel<<<gg128(NN, 2 * DD), 256, SMEM_BYTES>>>(root, rtf_wkv, kvtmp, NN, 2 * DD, DD);
    deint_kv_kernel<<<ndBlocks, 256>>>(kvtmp, k, v);
    cudaMemsetAsync(agg, 0, (size_t)NN * DD * sizeof(float));
    cudaMemsetAsync(s, 0, (size_t)NN * HH * sizeof(float));
    cross_fused_kernel<<<edgeBlocks, 256>>>(q, k, v, rtf_idx, rtf_idx + EE, s, agg, iscale);
    rcp_kernel<<<nhBlocks, 256>>>(s);
    norm_agg_kernel<<<ndBlocks, 256>>>(agg, s);
    tgemm_kernel<<<gg128(NN, DD), 256, SMEM_BYTES>>>(agg, rtf_wout, out + (size_t)NN * DD, NN, DD, DD);
}